// round 2
// baseline (speedup 1.0000x reference)
#include <cuda_runtime.h>
#include <math.h>

// Problem: feature [128, 64, 128] fp32 -> scalar contrastive loss.
// Flat rows r = i*64+j (N=8192), D=128. pos block for row r = columns [64*(r/64), +64).
// loss = mean_r( log(total_r) - log(pos_r) ), total_r = sum_c exp(10*f_r.f_c).

constexpr int N    = 8192;
constexpr int D    = 128;
constexpr int TILE = 128;
constexpr int TK   = 32;
constexpr float INV_T = 10.0f;

__device__ float g_fn[N * D];     // normalized features
__device__ float g_total[N];      // per-row total exp sum
__device__ float g_pos[N];        // per-row pos-block exp sum

// ---------------- Kernel 1: L2 normalize + zero accumulators ----------------
__global__ void normalize_kernel(const float* __restrict__ in) {
    int row  = blockIdx.x * 8 + (threadIdx.x >> 5);
    int lane = threadIdx.x & 31;
    const float4 v = ((const float4*)(in + (size_t)row * D))[lane];
    float ss = v.x * v.x + v.y * v.y + v.z * v.z + v.w * v.w;
    #pragma unroll
    for (int o = 16; o; o >>= 1) ss += __shfl_xor_sync(0xffffffffu, ss, o);
    float r = rsqrtf(ss);
    float4 o4 = make_float4(v.x * r, v.y * r, v.z * r, v.w * r);
    ((float4*)(g_fn + (size_t)row * D))[lane] = o4;
    if (lane == 0) { g_total[row] = 0.f; g_pos[row] = 0.f; }
}

// ---------------- Kernel 2: symmetric Gram tiles + fused exp/row-sums -------
__global__ __launch_bounds__(256, 2) void gram_kernel() {
    const int br = blockIdx.y, bc = blockIdx.x;
    if (bc < br) return;                       // upper triangle only

    __shared__ float As[TK][TILE + 4];
    __shared__ float Bs[TK][TILE + 4];
    __shared__ float sred[8][TILE];

    const int t  = threadIdx.x;                // 256 threads = 16x16
    const int tx = t & 15, ty = t >> 4;
    const int lrow0 = t >> 3;                  // 0..31
    const int kq    = (t & 7) * 4;             // 0,4,...,28

    const float* A  = g_fn + (size_t)br * TILE * D;
    const float* Bp = g_fn + (size_t)bc * TILE * D;

    float acc[8][8];
    #pragma unroll
    for (int i = 0; i < 8; i++)
        #pragma unroll
        for (int j = 0; j < 8; j++) acc[i][j] = 0.f;

    #pragma unroll
    for (int kc = 0; kc < D; kc += TK) {
        if (kc) __syncthreads();
        #pragma unroll
        for (int p = 0; p < 4; p++) {          // stage 128x32 of A and B, transposed
            int lr = lrow0 + p * 32;
            float4 a = *(const float4*)(A + (size_t)lr * D + kc + kq);
            As[kq + 0][lr] = a.x; As[kq + 1][lr] = a.y;
            As[kq + 2][lr] = a.z; As[kq + 3][lr] = a.w;
            float4 b = *(const float4*)(Bp + (size_t)lr * D + kc + kq);
            Bs[kq + 0][lr] = b.x; Bs[kq + 1][lr] = b.y;
            Bs[kq + 2][lr] = b.z; Bs[kq + 3][lr] = b.w;
        }
        __syncthreads();
        #pragma unroll
        for (int k = 0; k < TK; k++) {
            float a[8], b[8];
            *(float4*)(a)     = *(const float4*)&As[k][ty * 8];
            *(float4*)(a + 4) = *(const float4*)&As[k][ty * 8 + 4];
            *(float4*)(b)     = *(const float4*)&Bs[k][tx * 8];
            *(float4*)(b + 4) = *(const float4*)&Bs[k][tx * 8 + 4];
            #pragma unroll
            for (int i = 0; i < 8; i++)
                #pragma unroll
                for (int j = 0; j < 8; j++)
                    acc[i][j] = fmaf(a[i], b[j], acc[i][j]);
        }
    }

    // -------- epilogue: exp + row/col partial sums --------
    const bool diag = (br == bc);
    float rowsum[8], colsum[8];
    #pragma unroll
    for (int i = 0; i < 8; i++) { rowsum[i] = 0.f; colsum[i] = 0.f; }
    #pragma unroll
    for (int i = 0; i < 8; i++)
        #pragma unroll
        for (int j = 0; j < 8; j++) {
            float e = __expf(acc[i][j] * INV_T);
            rowsum[i] += e;
            colsum[j] += e;
        }

    const unsigned mask = 0xffffffffu;

    // row totals: reduce over the 16 lanes sharing ty (xor<16 stays in group)
    #pragma unroll
    for (int i = 0; i < 8; i++) {
        float v = rowsum[i];
        v += __shfl_xor_sync(mask, v, 8);
        v += __shfl_xor_sync(mask, v, 4);
        v += __shfl_xor_sync(mask, v, 2);
        v += __shfl_xor_sync(mask, v, 1);
        if ((t & 15) == 0)
            atomicAdd(&g_total[br * TILE + ty * 8 + i], v);
    }

    if (diag) {
        // pos exists only on diagonal tiles: column half must match row half.
        // Per-thread the match is uniform over its whole 8x8 sub-tile.
        const bool match = ((tx >> 3) == (ty >> 3));
        #pragma unroll
        for (int i = 0; i < 8; i++) {
            float v = match ? rowsum[i] : 0.f;
            v += __shfl_xor_sync(mask, v, 8);
            v += __shfl_xor_sync(mask, v, 4);
            v += __shfl_xor_sync(mask, v, 2);
            v += __shfl_xor_sync(mask, v, 1);
            if ((t & 15) == 0)
                atomicAdd(&g_pos[br * TILE + ty * 8 + i], v);
        }
    } else {
        // symmetric contribution: column sums of this tile are row partial
        // sums for rows in the bc tile.
        #pragma unroll
        for (int j = 0; j < 8; j++)
            colsum[j] += __shfl_xor_sync(mask, colsum[j], 16); // merge ty pairs
        const int w = t >> 5, lane = t & 31;
        if (lane < 16) {
            #pragma unroll
            for (int j = 0; j < 8; j++)
                sred[w][tx * 8 + j] = colsum[j];
        }
        __syncthreads();
        if (t < TILE) {
            float s = 0.f;
            #pragma unroll
            for (int w2 = 0; w2 < 8; w2++) s += sred[w2][t];
            atomicAdd(&g_total[bc * TILE + t], s);
        }
    }
}

// ---------------- Kernel 3: loss = mean(log(total) - log(pos)) --------------
__global__ void loss_kernel(float* __restrict__ out) {
    __shared__ float wsum[8];
    float s = 0.f;
    for (int r = threadIdx.x; r < N; r += 256)
        s += logf(g_total[r]) - logf(g_pos[r]);
    #pragma unroll
    for (int o = 16; o; o >>= 1) s += __shfl_xor_sync(0xffffffffu, s, o);
    const int lane = threadIdx.x & 31, w = threadIdx.x >> 5;
    if (lane == 0) wsum[w] = s;
    __syncthreads();
    if (threadIdx.x == 0) {
        float tot = 0.f;
        #pragma unroll
        for (int i = 0; i < 8; i++) tot += wsum[i];
        out[0] = tot / (float)N;
    }
}

// ---------------- launch -----------------------------------------------------
extern "C" void kernel_launch(void* const* d_in, const int* in_sizes, int n_in,
                              void* d_out, int out_size) {
    const float* feature = (const float*)d_in[0];
    normalize_kernel<<<N / 8, 256>>>(feature);
    gram_kernel<<<dim3(64, 64), 256>>>();
    loss_kernel<<<1, 256>>>((float*)d_out);
}

// round 4
// speedup vs baseline: 4.4233x; 4.4233x over previous
#include <cuda_runtime.h>
#include <cuda_fp16.h>
#include <cstdint>
#include <math.h>

// feature [128, 64, 128] fp32 -> scalar contrastive loss.
// N=8192 flat rows, D=128. pos block of row r = cols [64*(r/64), +64),
// entirely inside the 128-wide diagonal tile.
constexpr int N = 8192;
constexpr int D = 128;
constexpr float INV_T = 10.0f;

constexpr int ROWB = 272;                 // padded smem row stride (bytes)
constexpr int SMEM_BYTES = 2 * 128 * ROWB;  // A tile + B tile
constexpr int B_OFF = 128 * ROWB;

__device__ uint4 g_hv[N * D / 8];         // normalized features, fp16
__device__ float g_total[N];
__device__ float g_pos[N];
#define G_H ((__half*)g_hv)

__device__ __forceinline__ uint32_t smem_u32(const void* p) {
    uint32_t a;
    asm("{ .reg .u64 t; cvta.to.shared.u64 t, %1; cvt.u32.u64 %0, t; }"
        : "=r"(a) : "l"(p));
    return a;
}
__device__ __forceinline__ void ldmx4(uint32_t& r0, uint32_t& r1, uint32_t& r2,
                                      uint32_t& r3, uint32_t addr) {
    asm volatile("ldmatrix.sync.aligned.m8n8.x4.shared.b16 {%0,%1,%2,%3}, [%4];"
                 : "=r"(r0), "=r"(r1), "=r"(r2), "=r"(r3) : "r"(addr));
}
__device__ __forceinline__ void ldmx2(uint32_t& r0, uint32_t& r1, uint32_t addr) {
    asm volatile("ldmatrix.sync.aligned.m8n8.x2.shared.b16 {%0,%1}, [%2];"
                 : "=r"(r0), "=r"(r1) : "r"(addr));
}
__device__ __forceinline__ void mma16816(float* c, uint32_t a0, uint32_t a1,
                                         uint32_t a2, uint32_t a3,
                                         uint32_t b0, uint32_t b1) {
    asm volatile(
        "mma.sync.aligned.m16n8k16.row.col.f32.f16.f16.f32 "
        "{%0,%1,%2,%3}, {%4,%5,%6,%7}, {%8,%9}, {%0,%1,%2,%3};"
        : "+f"(c[0]), "+f"(c[1]), "+f"(c[2]), "+f"(c[3])
        : "r"(a0), "r"(a1), "r"(a2), "r"(a3), "r"(b0), "r"(b1));
}

// ---------------- Kernel 1: L2 normalize -> fp16, zero accumulators --------
__global__ void normalize_kernel(const float* __restrict__ in) {
    int row  = blockIdx.x * 8 + (threadIdx.x >> 5);
    int lane = threadIdx.x & 31;
    const float4 v = ((const float4*)(in + (size_t)row * D))[lane];
    float ss = v.x * v.x + v.y * v.y + v.z * v.z + v.w * v.w;
    #pragma unroll
    for (int o = 16; o; o >>= 1) ss += __shfl_xor_sync(0xffffffffu, ss, o);
    float r = rsqrtf(ss);
    union { __half2 h[2]; uint2 u; } pk;
    pk.h[0] = __floats2half2_rn(v.x * r, v.y * r);
    pk.h[1] = __floats2half2_rn(v.z * r, v.w * r);
    ((uint2*)g_hv)[row * 32 + lane] = pk.u;
    if (lane == 0) { g_total[row] = 0.f; g_pos[row] = 0.f; }
}

// ---------------- Kernel 2: HMMA Gram tile + fused exp/row+col sums --------
__global__ __launch_bounds__(256, 2) void gram_kernel() {
    extern __shared__ char smem[];
    const int br = blockIdx.y, bc = blockIdx.x;
    if (bc < br) return;                          // upper triangle only
    const bool diag = (br == bc);

    const int tid  = threadIdx.x;
    const int lane = tid & 31;
    const int wid  = tid >> 5;
    const int wrow = wid >> 2;                    // 0..1 : rows wrow*64..+64
    const int wcol = wid & 3;                     // 0..3 : cols wcol*32..+32
    const uint32_t sb = smem_u32(smem);

    // ---- stage tiles (row-major, 272B padded stride) ----
    const uint4* Ag = (const uint4*)(G_H + (size_t)br * 128 * D);
    const uint4* Bg = (const uint4*)(G_H + (size_t)bc * 128 * D);
    #pragma unroll
    for (int it = 0; it < 8; it++) {
        int idx = it * 256 + tid;                 // 2048 16B-chunks per tile
        int r = idx >> 4, c = idx & 15;
        *(uint4*)(smem + r * ROWB + c * 16) = Ag[idx];
        if (!diag) *(uint4*)(smem + B_OFF + r * ROWB + c * 16) = Bg[idx];
    }
    __syncthreads();

    const uint32_t boff = diag ? 0u : (uint32_t)B_OFF;

    // ldmatrix lane addresses
    uint32_t aAddr[4], bAddr[4];
    #pragma unroll
    for (int i = 0; i < 4; i++)
        aAddr[i] = sb + (wrow * 64 + i * 16 + (lane & 15)) * ROWB + (lane >> 4) * 16;
    #pragma unroll
    for (int j = 0; j < 4; j++)
        bAddr[j] = sb + boff + (wcol * 32 + j * 8 + (lane & 7)) * ROWB +
                   ((lane >> 3) & 1) * 16;

    float acc[4][4][4];
    #pragma unroll
    for (int i = 0; i < 4; i++)
        #pragma unroll
        for (int j = 0; j < 4; j++)
            #pragma unroll
            for (int r = 0; r < 4; r++) acc[i][j][r] = 0.f;

    #pragma unroll
    for (int ks = 0; ks < 8; ks++) {
        uint32_t b0[4], b1[4];
        #pragma unroll
        for (int j = 0; j < 4; j++) ldmx2(b0[j], b1[j], bAddr[j] + ks * 32);
        #pragma unroll
        for (int i = 0; i < 4; i++) {
            uint32_t a0, a1, a2, a3;
            ldmx4(a0, a1, a2, a3, aAddr[i] + ks * 32);
            #pragma unroll
            for (int j = 0; j < 4; j++)
                mma16816(acc[i][j], a0, a1, a2, a3, b0[j], b1[j]);
        }
    }

    // ---- epilogue: exp + per-thread row/col partials ----
    float rs[8], cs[8];
    #pragma unroll
    for (int q = 0; q < 8; q++) { rs[q] = 0.f; cs[q] = 0.f; }
    #pragma unroll
    for (int i = 0; i < 4; i++)
        #pragma unroll
        for (int j = 0; j < 4; j++) {
            float e0 = __expf(acc[i][j][0] * INV_T);
            float e1 = __expf(acc[i][j][1] * INV_T);
            float e2 = __expf(acc[i][j][2] * INV_T);
            float e3 = __expf(acc[i][j][3] * INV_T);
            rs[i * 2]     += e0 + e1;
            rs[i * 2 + 1] += e2 + e3;
            cs[j * 2]     += e0 + e2;
            cs[j * 2 + 1] += e1 + e3;
        }

    const unsigned m = 0xffffffffu;
    #pragma unroll
    for (int q = 0; q < 8; q++) {                 // rows: reduce lane bits 0,1
        rs[q] += __shfl_xor_sync(m, rs[q], 1);
        rs[q] += __shfl_xor_sync(m, rs[q], 2);
    }
    #pragma unroll
    for (int q = 0; q < 8; q++) {                 // cols: reduce lane bits 2,3,4
        cs[q] += __shfl_xor_sync(m, cs[q], 4);
        cs[q] += __shfl_xor_sync(m, cs[q], 8);
        cs[q] += __shfl_xor_sync(m, cs[q], 16);
    }

    __syncthreads();                              // tiles no longer needed
    float* sred = (float*)smem;                   // [4][128] row sums per wcol
    float* cred = (float*)(smem + 2048);          // [2][128] col sums per wrow

    if ((lane & 3) == 0) {
        #pragma unroll
        for (int i = 0; i < 4; i++)
            #pragma unroll
            for (int h = 0; h < 2; h++)
                sred[wcol * 128 + wrow * 64 + i * 16 + (lane >> 2) + h * 8] =
                    rs[i * 2 + h];
    }
    if (!diag && lane < 4) {
        #pragma unroll
        for (int j = 0; j < 4; j++)
            #pragma unroll
            for (int p = 0; p < 2; p++)
                cred[wrow * 128 + wcol * 32 + j * 8 + lane * 2 + p] =
                    cs[j * 2 + p];
    }
    __syncthreads();

    if (tid < 128) {
        float tot = sred[tid] + sred[128 + tid] + sred[256 + tid] + sred[384 + tid];
        atomicAdd(&g_total[br * 128 + tid], tot);
        if (diag) {
            int h = tid >> 6;                     // col half matching row half
            g_pos[br * 128 + tid] =
                sred[(2 * h) * 128 + tid] + sred[(2 * h + 1) * 128 + tid];
        }
    } else if (!diag) {
        int col = tid - 128;                      // symmetric: col sums -> rows of bc
        atomicAdd(&g_total[bc * 128 + col], cred[col] + cred[128 + col]);
    }
}

// ---------------- Kernel 3: loss = mean(log(total) - log(pos)) -------------
__global__ void loss_kernel(float* __restrict__ out) {
    __shared__ float wsum[8];
    float s = 0.f;
    for (int r = threadIdx.x; r < N; r += 256)
        s += logf(g_total[r]) - logf(g_pos[r]);
    #pragma unroll
    for (int o = 16; o; o >>= 1) s += __shfl_xor_sync(0xffffffffu, s, o);
    const int lane = threadIdx.x & 31, w = threadIdx.x >> 5;
    if (lane == 0) wsum[w] = s;
    __syncthreads();
    if (threadIdx.x == 0) {
        float tot = 0.f;
        #pragma unroll
        for (int i = 0; i < 8; i++) tot += wsum[i];
        out[0] = tot / (float)N;
    }
}

// ---------------- launch ----------------------------------------------------
extern "C" void kernel_launch(void* const* d_in, const int* in_sizes, int n_in,
                              void* d_out, int out_size) {
    const float* feature = (const float*)d_in[0];
    cudaFuncSetAttribute(gram_kernel,
                         cudaFuncAttributeMaxDynamicSharedMemorySize, SMEM_BYTES);
    normalize_kernel<<<N / 8, 256>>>(feature);
    gram_kernel<<<dim3(64, 64), 256, SMEM_BYTES>>>();
    loss_kernel<<<1, 256>>>((float*)d_out);
}

// round 5
// speedup vs baseline: 5.2516x; 1.1873x over previous
#include <cuda_runtime.h>
#include <cuda_fp16.h>
#include <cstdint>
#include <math.h>

constexpr int N = 8192;
constexpr int D = 128;
constexpr float INV_T = 10.0f;

constexpr int NT     = 64;
constexpr int NTILES = 2080;
constexpr int GRID   = 296;

constexpr int ROWB  = 272;
constexpr int ATILE = 128 * ROWB;
constexpr int SMEM_A   = 0;
constexpr int SMEM_B0  = ATILE;
constexpr int SMEM_B1  = 2 * ATILE;
constexpr int SMEM_RED = 3 * ATILE;
constexpr int SMEM_BYTES = 3 * ATILE + 2048;

__device__ uint4 g_hv[N * D / 8];
__device__ float g_total[N];
__device__ float g_pos[N];
#define G_H ((__half*)g_hv)

__device__ __forceinline__ uint32_t smem_u32(const void* p) {
    uint32_t a;
    asm("{ .reg .u64 t; cvta.to.shared.u64 t, %1; cvt.u32.u64 %0, t; }"
        : "=r"(a) : "l"(p));
    return a;
}
__device__ __forceinline__ void ldmx4(uint32_t& r0, uint32_t& r1, uint32_t& r2,
                                      uint32_t& r3, uint32_t addr) {
    asm volatile("ldmatrix.sync.aligned.m8n8.x4.shared.b16 {%0,%1,%2,%3}, [%4];"
                 : "=r"(r0), "=r"(r1), "=r"(r2), "=r"(r3) : "r"(addr));
}
__device__ __forceinline__ void ldmx2(uint32_t& r0, uint32_t& r1, uint32_t addr) {
    asm volatile("ldmatrix.sync.aligned.m8n8.x2.shared.b16 {%0,%1}, [%2];"
                 : "=r"(r0), "=r"(r1) : "r"(addr));
}
__device__ __forceinline__ void mma16816(float* c, uint32_t a0, uint32_t a1,
                                         uint32_t a2, uint32_t a3,
                                         uint32_t b0, uint32_t b1) {
    asm volatile(
        "mma.sync.aligned.m16n8k16.row.col.f32.f16.f16.f32 "
        "{%0,%1,%2,%3}, {%4,%5,%6,%7}, {%8,%9}, {%0,%1,%2,%3};"
        : "+f"(c[0]), "+f"(c[1]), "+f"(c[2]), "+f"(c[3])
        : "r"(a0), "r"(a1), "r"(a2), "r"(a3), "r"(b0), "r"(b1));
}
__device__ __forceinline__ void cpa16(uint32_t sdst, const void* gsrc) {
    asm volatile("cp.async.cg.shared.global [%0], [%1], 16;"
                 :: "r"(sdst), "l"(gsrc) : "memory");
}
__device__ __forceinline__ void cpa_commit() {
    asm volatile("cp.async.commit_group;" ::: "memory");
}
__device__ __forceinline__ void cpa_wait0() {
    asm volatile("cp.async.wait_group 0;" ::: "memory");
}

__device__ __forceinline__ void stage_tile(uint32_t sdst, const uint4* gsrc, int tid) {
    #pragma unroll
    for (int it = 0; it < 8; it++) {
        int idx = it * 256 + tid;
        int r = idx >> 4, c = idx & 15;
        cpa16(sdst + r * ROWB + c * 16, gsrc + idx);
    }
}

__global__ void normalize_kernel(const float* __restrict__ in) {
    int row  = blockIdx.x * 8 + (threadIdx.x >> 5);
    int lane = threadIdx.x & 31;
    const float4 v = ((const float4*)(in + (size_t)row * D))[lane];
    float ss = v.x * v.x + v.y * v.y + v.z * v.z + v.w * v.w;
    #pragma unroll
    for (int o = 16; o; o >>= 1) ss += __shfl_xor_sync(0xffffffffu, ss, o);
    float r = rsqrtf(ss);
    union { __half2 h[2]; uint2 u; } pk;
    pk.h[0] = __floats2half2_rn(v.x * r, v.y * r);
    pk.h[1] = __floats2half2_rn(v.z * r, v.w * r);
    ((uint2*)g_hv)[row * 32 + lane] = pk.u;
    if (lane == 0) { g_total[row] = 0.f; g_pos[row] = 0.f; }
}

__global__ __launch_bounds__(256, 2) void gram_kernel() {
    extern __shared__ char smem[];
    const int tid  = threadIdx.x;
    const int lane = tid & 31;
    const int wid  = tid >> 5;
    const int wrow = wid >> 2;
    const int wcol = wid & 3;
    const uint32_t sb = smem_u32(smem);
    float* sred = (float*)(smem + SMEM_RED);

    int t  = (int)((long long)blockIdx.x * NTILES / GRID);
    int t1 = (int)((long long)(blockIdx.x + 1) * NTILES / GRID);
    int br = 0, base = 0;
    while (t >= base + (NT - br)) { base += NT - br; br++; }
    int bc = br + (t - base);

    uint32_t aAddr[4];
    #pragma unroll
    for (int i = 0; i < 4; i++)
        aAddr[i] = sb + SMEM_A +
                   (wrow * 64 + i * 16 + (lane & 15)) * ROWB + (lane >> 4) * 16;
    const uint32_t bLane = (wcol * 32 + (lane & 7)) * ROWB + ((lane >> 3) & 1) * 16;

    while (t < t1) {
        stage_tile(sb + SMEM_A, (const uint4*)(G_H + (size_t)br * 128 * D), tid);
        stage_tile(sb + SMEM_B0, (const uint4*)(G_H + (size_t)bc * 128 * D), tid);
        cpa_commit(); cpa_wait0();
        __syncthreads();

        float rs_acc[8];
        #pragma unroll
        for (int q = 0; q < 8; q++) rs_acc[q] = 0.f;
        int buf = 0;

        for (;;) {
            const bool diag = (bc == br);
            const bool next_same = (t + 1 < t1) && (bc + 1 < NT);
            if (next_same) {
                stage_tile(sb + (buf ? SMEM_B0 : SMEM_B1),
                           (const uint4*)(G_H + (size_t)(bc + 1) * 128 * D), tid);
                cpa_commit();
            }

            const uint32_t bbase = sb + (buf ? SMEM_B1 : SMEM_B0) + bLane;
            float acc[4][4][4];
            #pragma unroll
            for (int i = 0; i < 4; i++)
                #pragma unroll
                for (int j = 0; j < 4; j++)
                    #pragma unroll
                    for (int r = 0; r < 4; r++) acc[i][j][r] = 0.f;
            #pragma unroll
            for (int ks = 0; ks < 8; ks++) {
                uint32_t b0[4], b1[4];
                #pragma unroll
                for (int j = 0; j < 4; j++)
                    ldmx2(b0[j], b1[j], bbase + j * 8 * ROWB + ks * 32);
                #pragma unroll
                for (int i = 0; i < 4; i++) {
                    uint32_t a0, a1, a2, a3;
                    ldmx4(a0, a1, a2, a3, aAddr[i] + ks * 32);
                    #pragma unroll
                    for (int j = 0; j < 4; j++)
                        mma16816(acc[i][j], a0, a1, a2, a3, b0[j], b1[j]);
                }
            }

            const unsigned m = 0xffffffffu;
            if (diag) {
                float rt[8];
                #pragma unroll
                for (int q = 0; q < 8; q++) rt[q] = 0.f;
                #pragma unroll
                for (int i = 0; i < 4; i++)
                    #pragma unroll
                    for (int j = 0; j < 4; j++) {
                        rt[i*2]   += __expf(acc[i][j][0]*INV_T) + __expf(acc[i][j][1]*INV_T);
                        rt[i*2+1] += __expf(acc[i][j][2]*INV_T) + __expf(acc[i][j][3]*INV_T);
                    }
                #pragma unroll
                for (int q = 0; q < 8; q++) {
                    rt[q] += __shfl_xor_sync(m, rt[q], 1);
                    rt[q] += __shfl_xor_sync(m, rt[q], 2);
                    if ((lane & 3) == 0) rs_acc[q] += rt[q];  // exact: flush re-reduces
                }
                if ((lane & 3) == 0) {
                    #pragma unroll
                    for (int i = 0; i < 4; i++)
                        #pragma unroll
                        for (int h = 0; h < 2; h++)
                            sred[wcol*128 + wrow*64 + i*16 + (lane>>2) + h*8] = rt[i*2+h];
                }
                cpa_wait0();
                __syncthreads();
                if (tid < 128) {
                    int h = tid >> 6;
                    g_pos[br * 128 + tid] =
                        sred[(2*h)*128 + tid] + sred[(2*h+1)*128 + tid];
                }
                __syncthreads();
            } else {
                float cs[8];
                #pragma unroll
                for (int q = 0; q < 8; q++) cs[q] = 0.f;
                #pragma unroll
                for (int i = 0; i < 4; i++)
                    #pragma unroll
                    for (int j = 0; j < 4; j++) {
                        float e0 = __expf(acc[i][j][0] * INV_T);
                        float e1 = __expf(acc[i][j][1] * INV_T);
                        float e2 = __expf(acc[i][j][2] * INV_T);
                        float e3 = __expf(acc[i][j][3] * INV_T);
                        rs_acc[i*2]   += e0 + e1;
                        rs_acc[i*2+1] += e2 + e3;
                        cs[j*2]   += e0 + e2;
                        cs[j*2+1] += e1 + e3;
                    }
                #pragma unroll
                for (int q = 0; q < 8; q++) {
                    cs[q] += __shfl_xor_sync(m, cs[q], 4);
                    cs[q] += __shfl_xor_sync(m, cs[q], 8);
                    cs[q] += __shfl_xor_sync(m, cs[q], 16);
                }
                if (lane < 4) {
                    #pragma unroll
                    for (int j = 0; j < 4; j++)
                        #pragma unroll
                        for (int p = 0; p < 2; p++)
                            sred[wrow*128 + wcol*32 + j*8 + lane*2 + p] = cs[j*2+p];
                }
                cpa_wait0();
                __syncthreads();
                if (tid < 128)
                    atomicAdd(&g_total[bc * 128 + tid],
                              sred[tid] + sred[128 + tid]);
                __syncthreads();
            }

            t++; bc++;
            if (!next_same) break;
            buf ^= 1;
        }

        const unsigned m = 0xffffffffu;
        float rf[8];
        #pragma unroll
        for (int q = 0; q < 8; q++) {
            float v = rs_acc[q];
            v += __shfl_xor_sync(m, v, 1);
            v += __shfl_xor_sync(m, v, 2);
            rf[q] = v;
        }
        if ((lane & 3) == 0) {
            #pragma unroll
            for (int i = 0; i < 4; i++)
                #pragma unroll
                for (int h = 0; h < 2; h++)
                    sred[wcol*128 + wrow*64 + i*16 + (lane>>2) + h*8] = rf[i*2+h];
        }
        __syncthreads();
        if (tid < 128)
            atomicAdd(&g_total[br * 128 + tid],
                      sred[tid] + sred[128+tid] + sred[256+tid] + sred[384+tid]);
        __syncthreads();

        if (t < t1 && bc >= NT) { br++; bc = br; }
    }
}

__global__ void loss_kernel(float* __restrict__ out) {
    __shared__ float wsum[8];
    float s = 0.f;
    for (int r = threadIdx.x; r < N; r += 256)
        s += __logf(g_total[r]) - __logf(g_pos[r]);
    #pragma unroll
    for (int o = 16; o; o >>= 1) s += __shfl_xor_sync(0xffffffffu, s, o);
    const int lane = threadIdx.x & 31, w = threadIdx.x >> 5;
    if (lane == 0) wsum[w] = s;
    __syncthreads();
    if (threadIdx.x == 0) {
        float tot = 0.f;
        #pragma unroll
        for (int i = 0; i < 8; i++) tot += wsum[i];
        out[0] = tot / (float)N;
    }
}

extern "C" void kernel_launch(void* const* d_in, const int* in_sizes, int n_in,
                              void* d_out, int out_size) {
    const float* feature = (const float*)d_in[0];
    cudaFuncSetAttribute(gram_kernel,
                         cudaFuncAttributeMaxDynamicSharedMemorySize, SMEM_BYTES);
    normalize_kernel<<<N / 8, 256>>>(feature);
    gram_kernel<<<GRID, 256, SMEM_BYTES>>>();
    loss_kernel<<<1, 256>>>((float*)d_out);
}

// round 6
// speedup vs baseline: 5.5394x; 1.0548x over previous
#include <cuda_runtime.h>
#include <cuda_fp16.h>
#include <cstdint>
#include <math.h>

constexpr int N = 8192;
constexpr int D = 128;
constexpr float INV_T = 10.0f;

constexpr int NT     = 64;
constexpr int NTILES = 2080;
constexpr int GRID   = 296;

constexpr int ROWB  = 272;
constexpr int ATILE = 128 * ROWB;
constexpr int SMEM_A   = 0;
constexpr int SMEM_B0  = ATILE;
constexpr int SMEM_B1  = 2 * ATILE;
constexpr int SMEM_RED = 3 * ATILE;
constexpr int SMEM_BYTES = 3 * ATILE + 2048;

__device__ uint4 g_hv[N * D / 8];
__device__ float g_total[N];
__device__ float g_pos[N];
__device__ float g_loss;
__device__ unsigned g_cnt;
#define G_H ((__half*)g_hv)

__device__ __forceinline__ uint32_t smem_u32(const void* p) {
    uint32_t a;
    asm("{ .reg .u64 t; cvta.to.shared.u64 t, %1; cvt.u32.u64 %0, t; }"
        : "=r"(a) : "l"(p));
    return a;
}
__device__ __forceinline__ void ldmx4(uint32_t& r0, uint32_t& r1, uint32_t& r2,
                                      uint32_t& r3, uint32_t addr) {
    asm volatile("ldmatrix.sync.aligned.m8n8.x4.shared.b16 {%0,%1,%2,%3}, [%4];"
                 : "=r"(r0), "=r"(r1), "=r"(r2), "=r"(r3) : "r"(addr));
}
__device__ __forceinline__ void ldmx2(uint32_t& r0, uint32_t& r1, uint32_t addr) {
    asm volatile("ldmatrix.sync.aligned.m8n8.x2.shared.b16 {%0,%1}, [%2];"
                 : "=r"(r0), "=r"(r1) : "r"(addr));
}
__device__ __forceinline__ void mma16816(float* c, uint32_t a0, uint32_t a1,
                                         uint32_t a2, uint32_t a3,
                                         uint32_t b0, uint32_t b1) {
    asm volatile(
        "mma.sync.aligned.m16n8k16.row.col.f32.f16.f16.f32 "
        "{%0,%1,%2,%3}, {%4,%5,%6,%7}, {%8,%9}, {%0,%1,%2,%3};"
        : "+f"(c[0]), "+f"(c[1]), "+f"(c[2]), "+f"(c[3])
        : "r"(a0), "r"(a1), "r"(a2), "r"(a3), "r"(b0), "r"(b1));
}
__device__ __forceinline__ void cpa16(uint32_t sdst, const void* gsrc) {
    asm volatile("cp.async.cg.shared.global [%0], [%1], 16;"
                 :: "r"(sdst), "l"(gsrc) : "memory");
}
__device__ __forceinline__ void cpa_commit() {
    asm volatile("cp.async.commit_group;" ::: "memory");
}
__device__ __forceinline__ void cpa_wait0() {
    asm volatile("cp.async.wait_group 0;" ::: "memory");
}

__device__ __forceinline__ void stage_tile(uint32_t sdst, const uint4* gsrc, int tid) {
    #pragma unroll
    for (int it = 0; it < 8; it++) {
        int idx = it * 256 + tid;
        int r = idx >> 4, c = idx & 15;
        cpa16(sdst + r * ROWB + c * 16, gsrc + idx);
    }
}

// ---------------- Kernel 1: normalize (4 rows/warp, MLP=4) -----------------
__global__ void normalize_kernel(const float* __restrict__ in) {
    const int wid  = threadIdx.x >> 5;
    const int lane = threadIdx.x & 31;
    const int rb   = blockIdx.x * 32 + wid * 4;

    float4 v[4];
    #pragma unroll
    for (int r = 0; r < 4; r++)
        v[r] = ((const float4*)(in + (size_t)(rb + r) * D))[lane];

    float ss[4];
    #pragma unroll
    for (int r = 0; r < 4; r++)
        ss[r] = v[r].x * v[r].x + v[r].y * v[r].y +
                v[r].z * v[r].z + v[r].w * v[r].w;
    #pragma unroll
    for (int o = 16; o; o >>= 1)
        #pragma unroll
        for (int r = 0; r < 4; r++)
            ss[r] += __shfl_xor_sync(0xffffffffu, ss[r], o);

    #pragma unroll
    for (int r = 0; r < 4; r++) {
        float sc = rsqrtf(ss[r]);
        union { __half2 h[2]; uint2 u; } pk;
        pk.h[0] = __floats2half2_rn(v[r].x * sc, v[r].y * sc);
        pk.h[1] = __floats2half2_rn(v[r].z * sc, v[r].w * sc);
        ((uint2*)g_hv)[(rb + r) * 32 + lane] = pk.u;
    }
    if (lane < 4) { g_total[rb + lane] = 0.f; g_pos[rb + lane] = 0.f; }
    if (blockIdx.x == 0 && threadIdx.x == 0) { g_loss = 0.f; g_cnt = 0u; }
}

// ---------------- Kernel 2: persistent HMMA Gram ----------------------------
__global__ __launch_bounds__(256, 2) void gram_kernel() {
    extern __shared__ char smem[];
    const int tid  = threadIdx.x;
    const int lane = tid & 31;
    const int wid  = tid >> 5;
    const int wrow = wid >> 2;
    const int wcol = wid & 3;
    const uint32_t sb = smem_u32(smem);
    float* sred = (float*)(smem + SMEM_RED);

    int t  = (int)((long long)blockIdx.x * NTILES / GRID);
    int t1 = (int)((long long)(blockIdx.x + 1) * NTILES / GRID);
    int br = 0, base = 0;
    while (t >= base + (NT - br)) { base += NT - br; br++; }
    int bc = br + (t - base);

    uint32_t aAddr[4];
    #pragma unroll
    for (int i = 0; i < 4; i++)
        aAddr[i] = sb + SMEM_A +
                   (wrow * 64 + i * 16 + (lane & 15)) * ROWB + (lane >> 4) * 16;
    const uint32_t bLane = (wcol * 32 + (lane & 7)) * ROWB + ((lane >> 3) & 1) * 16;

    while (t < t1) {
        stage_tile(sb + SMEM_A, (const uint4*)(G_H + (size_t)br * 128 * D), tid);
        stage_tile(sb + SMEM_B0, (const uint4*)(G_H + (size_t)bc * 128 * D), tid);
        cpa_commit(); cpa_wait0();
        __syncthreads();

        float rs_acc[8];
        #pragma unroll
        for (int q = 0; q < 8; q++) rs_acc[q] = 0.f;
        int buf = 0;

        for (;;) {
            const bool diag = (bc == br);
            const bool next_same = (t + 1 < t1) && (bc + 1 < NT);
            if (next_same) {
                stage_tile(sb + (buf ? SMEM_B0 : SMEM_B1),
                           (const uint4*)(G_H + (size_t)(bc + 1) * 128 * D), tid);
                cpa_commit();
            }

            const uint32_t bbase = sb + (buf ? SMEM_B1 : SMEM_B0) + bLane;
            float acc[4][4][4];
            #pragma unroll
            for (int i = 0; i < 4; i++)
                #pragma unroll
                for (int j = 0; j < 4; j++)
                    #pragma unroll
                    for (int r = 0; r < 4; r++) acc[i][j][r] = 0.f;
            #pragma unroll
            for (int ks = 0; ks < 8; ks++) {
                uint32_t b0[4], b1[4];
                #pragma unroll
                for (int j = 0; j < 4; j++)
                    ldmx2(b0[j], b1[j], bbase + j * 8 * ROWB + ks * 32);
                #pragma unroll
                for (int i = 0; i < 4; i++) {
                    uint32_t a0, a1, a2, a3;
                    ldmx4(a0, a1, a2, a3, aAddr[i] + ks * 32);
                    #pragma unroll
                    for (int j = 0; j < 4; j++)
                        mma16816(acc[i][j], a0, a1, a2, a3, b0[j], b1[j]);
                }
            }

            const unsigned m = 0xffffffffu;
            if (diag) {
                float rt[8];
                #pragma unroll
                for (int q = 0; q < 8; q++) rt[q] = 0.f;
                #pragma unroll
                for (int i = 0; i < 4; i++)
                    #pragma unroll
                    for (int j = 0; j < 4; j++) {
                        rt[i*2]   += __expf(acc[i][j][0]*INV_T) + __expf(acc[i][j][1]*INV_T);
                        rt[i*2+1] += __expf(acc[i][j][2]*INV_T) + __expf(acc[i][j][3]*INV_T);
                    }
                #pragma unroll
                for (int q = 0; q < 8; q++) {
                    rt[q] += __shfl_xor_sync(m, rt[q], 1);
                    rt[q] += __shfl_xor_sync(m, rt[q], 2);
                    if ((lane & 3) == 0) rs_acc[q] += rt[q];  // flush re-reduces
                }
                if ((lane & 3) == 0) {
                    #pragma unroll
                    for (int i = 0; i < 4; i++)
                        #pragma unroll
                        for (int h = 0; h < 2; h++)
                            sred[wcol*128 + wrow*64 + i*16 + (lane>>2) + h*8] = rt[i*2+h];
                }
                cpa_wait0();
                __syncthreads();
                if (tid < 128) {
                    int h = tid >> 6;
                    g_pos[br * 128 + tid] =
                        sred[(2*h)*128 + tid] + sred[(2*h+1)*128 + tid];
                }
                __syncthreads();
            } else {
                // off-diag: sync-free column epilogue (direct atomics)
                float cs[8];
                #pragma unroll
                for (int q = 0; q < 8; q++) cs[q] = 0.f;
                #pragma unroll
                for (int i = 0; i < 4; i++)
                    #pragma unroll
                    for (int j = 0; j < 4; j++) {
                        float e0 = __expf(acc[i][j][0] * INV_T);
                        float e1 = __expf(acc[i][j][1] * INV_T);
                        float e2 = __expf(acc[i][j][2] * INV_T);
                        float e3 = __expf(acc[i][j][3] * INV_T);
                        rs_acc[i*2]   += e0 + e1;
                        rs_acc[i*2+1] += e2 + e3;
                        cs[j*2]   += e0 + e2;
                        cs[j*2+1] += e1 + e3;
                    }
                #pragma unroll
                for (int q = 0; q < 8; q++) {
                    cs[q] += __shfl_xor_sync(m, cs[q], 4);
                    cs[q] += __shfl_xor_sync(m, cs[q], 8);
                    cs[q] += __shfl_xor_sync(m, cs[q], 16);
                }
                if (lane < 4) {
                    const int colbase = bc * 128 + wcol * 32 + lane * 2;
                    #pragma unroll
                    for (int j = 0; j < 4; j++) {
                        atomicAdd(&g_total[colbase + j * 8],     cs[j*2]);
                        atomicAdd(&g_total[colbase + j * 8 + 1], cs[j*2+1]);
                    }
                }
                cpa_wait0();
                __syncthreads();
            }

            t++; bc++;
            if (!next_same) break;
            buf ^= 1;
        }

        // flush accumulated row sums for band br
        __syncthreads();                 // protect sred (diag may have just read)
        const unsigned m = 0xffffffffu;
        float rf[8];
        #pragma unroll
        for (int q = 0; q < 8; q++) {
            float v = rs_acc[q];
            v += __shfl_xor_sync(m, v, 1);
            v += __shfl_xor_sync(m, v, 2);
            rf[q] = v;
        }
        if ((lane & 3) == 0) {
            #pragma unroll
            for (int i = 0; i < 4; i++)
                #pragma unroll
                for (int h = 0; h < 2; h++)
                    sred[wcol*128 + wrow*64 + i*16 + (lane>>2) + h*8] = rf[i*2+h];
        }
        __syncthreads();
        if (tid < 128)
            atomicAdd(&g_total[br * 128 + tid],
                      sred[tid] + sred[128+tid] + sred[256+tid] + sred[384+tid]);
        __syncthreads();

        if (t < t1 && bc >= NT) { br++; bc = br; }
    }
}

// ---------------- Kernel 3: parallel loss with last-block finalize ---------
__global__ void loss_kernel(float* __restrict__ out) {
    __shared__ float wsum[8];
    const int r = blockIdx.x * 256 + threadIdx.x;     // grid 32 -> 8192 threads
    float s = __logf(g_total[r]) - __logf(g_pos[r]);
    #pragma unroll
    for (int o = 16; o; o >>= 1) s += __shfl_xor_sync(0xffffffffu, s, o);
    const int lane = threadIdx.x & 31, w = threadIdx.x >> 5;
    if (lane == 0) wsum[w] = s;
    __syncthreads();
    if (threadIdx.x == 0) {
        float bs = 0.f;
        #pragma unroll
        for (int i = 0; i < 8; i++) bs += wsum[i];
        atomicAdd(&g_loss, bs);
        __threadfence();
        unsigned old = atomicAdd(&g_cnt, 1u);
        if (old == gridDim.x - 1) {
            __threadfence();
            float tot = atomicAdd(&g_loss, 0.f);      // forced L2 read
            out[0] = tot / (float)N;
        }
    }
}

// ---------------- launch ----------------------------------------------------
extern "C" void kernel_launch(void* const* d_in, const int* in_sizes, int n_in,
                              void* d_out, int out_size) {
    const float* feature = (const float*)d_in[0];
    cudaFuncSetAttribute(gram_kernel,
                         cudaFuncAttributeMaxDynamicSharedMemorySize, SMEM_BYTES);
    normalize_kernel<<<N / 32, 256>>>(feature);
    gram_kernel<<<GRID, 256, SMEM_BYTES>>>();
    loss_kernel<<<32, 256>>>((float*)d_out);
}

// round 7
// speedup vs baseline: 5.8318x; 1.0528x over previous
#include <cuda_runtime.h>
#include <cuda_fp16.h>
#include <cstdint>
#include <math.h>

constexpr int N = 8192;
constexpr int D = 128;
constexpr float SCALE_L2E = 14.4269504088896f;   // 10 * log2(e)

constexpr int NT     = 64;
constexpr int NTILES = 2080;
constexpr int GRID   = 296;

constexpr int ROWB  = 272;
constexpr int ATILE = 128 * ROWB;
constexpr int SMEM_A   = 0;
constexpr int SMEM_B0  = ATILE;
constexpr int SMEM_B1  = 2 * ATILE;
constexpr int SMEM_RED = 3 * ATILE;
constexpr int SMEM_BYTES = 3 * ATILE + 2048;

__device__ uint4 g_hv[N * D / 8];
__device__ float g_total[N];
__device__ float g_pos[N];
__device__ float g_loss;
__device__ unsigned g_cnt;
#define G_H ((__half*)g_hv)

__device__ __forceinline__ uint32_t smem_u32(const void* p) {
    uint32_t a;
    asm("{ .reg .u64 t; cvta.to.shared.u64 t, %1; cvt.u32.u64 %0, t; }"
        : "=r"(a) : "l"(p));
    return a;
}
__device__ __forceinline__ void ldmx4(uint32_t& r0, uint32_t& r1, uint32_t& r2,
                                      uint32_t& r3, uint32_t addr) {
    asm volatile("ldmatrix.sync.aligned.m8n8.x4.shared.b16 {%0,%1,%2,%3}, [%4];"
                 : "=r"(r0), "=r"(r1), "=r"(r2), "=r"(r3) : "r"(addr));
}
__device__ __forceinline__ void mma16816(float* c, uint32_t a0, uint32_t a1,
                                         uint32_t a2, uint32_t a3,
                                         uint32_t b0, uint32_t b1) {
    asm volatile(
        "mma.sync.aligned.m16n8k16.row.col.f32.f16.f16.f32 "
        "{%0,%1,%2,%3}, {%4,%5,%6,%7}, {%8,%9}, {%0,%1,%2,%3};"
        : "+f"(c[0]), "+f"(c[1]), "+f"(c[2]), "+f"(c[3])
        : "r"(a0), "r"(a1), "r"(a2), "r"(a3), "r"(b0), "r"(b1));
}
__device__ __forceinline__ float fast_ex2(float x) {
    float r;
    asm("ex2.approx.ftz.f32 %0, %1;" : "=f"(r) : "f"(x));
    return r;
}
__device__ __forceinline__ void cpa16(uint32_t sdst, const void* gsrc) {
    asm volatile("cp.async.cg.shared.global [%0], [%1], 16;"
                 :: "r"(sdst), "l"(gsrc) : "memory");
}
__device__ __forceinline__ void cpa_commit() {
    asm volatile("cp.async.commit_group;" ::: "memory");
}
__device__ __forceinline__ void cpa_wait0() {
    asm volatile("cp.async.wait_group 0;" ::: "memory");
}

__device__ __forceinline__ void stage_tile(uint32_t sdst, const uint4* gsrc, int tid) {
    #pragma unroll
    for (int it = 0; it < 8; it++) {
        int idx = it * 256 + tid;
        int r = idx >> 4, c = idx & 15;
        cpa16(sdst + r * ROWB + c * 16, gsrc + idx);
    }
}

// ---------------- Kernel 1: normalize (2 rows/warp) ------------------------
__global__ void normalize_kernel(const float* __restrict__ in) {
    const int wid  = threadIdx.x >> 5;
    const int lane = threadIdx.x & 31;
    const int rb   = blockIdx.x * 16 + wid * 2;

    float4 v[2];
    #pragma unroll
    for (int r = 0; r < 2; r++)
        v[r] = ((const float4*)(in + (size_t)(rb + r) * D))[lane];

    float ss[2];
    #pragma unroll
    for (int r = 0; r < 2; r++)
        ss[r] = v[r].x * v[r].x + v[r].y * v[r].y +
                v[r].z * v[r].z + v[r].w * v[r].w;
    #pragma unroll
    for (int o = 16; o; o >>= 1)
        #pragma unroll
        for (int r = 0; r < 2; r++)
            ss[r] += __shfl_xor_sync(0xffffffffu, ss[r], o);

    #pragma unroll
    for (int r = 0; r < 2; r++) {
        float sc = rsqrtf(ss[r]);
        union { __half2 h[2]; uint2 u; } pk;
        pk.h[0] = __floats2half2_rn(v[r].x * sc, v[r].y * sc);
        pk.h[1] = __floats2half2_rn(v[r].z * sc, v[r].w * sc);
        ((uint2*)g_hv)[(rb + r) * 32 + lane] = pk.u;
    }
    if (lane < 2) { g_total[rb + lane] = 0.f; g_pos[rb + lane] = 0.f; }
    if (blockIdx.x == 0 && threadIdx.x == 0) { g_loss = 0.f; g_cnt = 0u; }
}

// ---------------- Kernel 2: persistent HMMA Gram ----------------------------
__global__ __launch_bounds__(256, 2) void gram_kernel() {
    extern __shared__ char smem[];
    const int tid  = threadIdx.x;
    const int lane = tid & 31;
    const int wid  = tid >> 5;
    const int wrow = wid >> 2;
    const int wcol = wid & 3;
    const uint32_t sb = smem_u32(smem);
    float* sred = (float*)(smem + SMEM_RED);

    int t  = (int)((long long)blockIdx.x * NTILES / GRID);
    int t1 = (int)((long long)(blockIdx.x + 1) * NTILES / GRID);
    int br = 0, base = 0;
    while (t >= base + (NT - br)) { base += NT - br; br++; }
    int bc = br + (t - base);

    uint32_t aAddr[4];
    #pragma unroll
    for (int i = 0; i < 4; i++)
        aAddr[i] = sb + SMEM_A +
                   (wrow * 64 + i * 16 + (lane & 15)) * ROWB + (lane >> 4) * 16;
    // ldmx4 B: j-pair p covers 16 cols; lanes 0-7 m0(rows,chunk0), 8-15 m1(chunk1),
    // 16-23 m2(rows+8,chunk0), 24-31 m3(rows+8,chunk1)
    const uint32_t bLane = (wcol * 32 + (lane & 7) + ((lane >> 4) & 1) * 8) * ROWB +
                           ((lane >> 3) & 1) * 16;

    while (t < t1) {
        stage_tile(sb + SMEM_A, (const uint4*)(G_H + (size_t)br * 128 * D), tid);
        stage_tile(sb + SMEM_B0, (const uint4*)(G_H + (size_t)bc * 128 * D), tid);
        cpa_commit(); cpa_wait0();
        __syncthreads();

        float rs_acc[8];
        #pragma unroll
        for (int q = 0; q < 8; q++) rs_acc[q] = 0.f;
        int buf = 0;

        for (;;) {
            const bool diag = (bc == br);
            const bool next_same = (t + 1 < t1) && (bc + 1 < NT);
            if (next_same) {
                stage_tile(sb + (buf ? SMEM_B0 : SMEM_B1),
                           (const uint4*)(G_H + (size_t)(bc + 1) * 128 * D), tid);
                cpa_commit();
            }

            const uint32_t bbase = sb + (buf ? SMEM_B1 : SMEM_B0) + bLane;
            float acc[4][4][4];
            #pragma unroll
            for (int i = 0; i < 4; i++)
                #pragma unroll
                for (int j = 0; j < 4; j++)
                    #pragma unroll
                    for (int r = 0; r < 4; r++) acc[i][j][r] = 0.f;

            // B fragments double-buffered across ks
            uint32_t bf[2][8];
            ldmx4(bf[0][0], bf[0][1], bf[0][2], bf[0][3], bbase);
            ldmx4(bf[0][4], bf[0][5], bf[0][6], bf[0][7], bbase + 16 * ROWB);
            #pragma unroll
            for (int ks = 0; ks < 8; ks++) {
                const int cur = ks & 1, nxt = cur ^ 1;
                if (ks < 7) {
                    ldmx4(bf[nxt][0], bf[nxt][1], bf[nxt][2], bf[nxt][3],
                          bbase + (ks + 1) * 32);
                    ldmx4(bf[nxt][4], bf[nxt][5], bf[nxt][6], bf[nxt][7],
                          bbase + 16 * ROWB + (ks + 1) * 32);
                }
                #pragma unroll
                for (int i = 0; i < 4; i++) {
                    uint32_t a0, a1, a2, a3;
                    ldmx4(a0, a1, a2, a3, aAddr[i] + ks * 32);
                    #pragma unroll
                    for (int j = 0; j < 4; j++)
                        mma16816(acc[i][j], a0, a1, a2, a3,
                                 bf[cur][j * 2], bf[cur][j * 2 + 1]);
                }
            }

            const unsigned m = 0xffffffffu;
            if (diag) {
                float rt[8];
                #pragma unroll
                for (int q = 0; q < 8; q++) rt[q] = 0.f;
                #pragma unroll
                for (int i = 0; i < 4; i++)
                    #pragma unroll
                    for (int j = 0; j < 4; j++) {
                        rt[i*2]   += fast_ex2(acc[i][j][0] * SCALE_L2E) +
                                     fast_ex2(acc[i][j][1] * SCALE_L2E);
                        rt[i*2+1] += fast_ex2(acc[i][j][2] * SCALE_L2E) +
                                     fast_ex2(acc[i][j][3] * SCALE_L2E);
                    }
                #pragma unroll
                for (int q = 0; q < 8; q++) {
                    rt[q] += __shfl_xor_sync(m, rt[q], 1);
                    rt[q] += __shfl_xor_sync(m, rt[q], 2);
                    if ((lane & 3) == 0) rs_acc[q] += rt[q];   // flush re-reduces
                }
                if ((lane & 3) == 0) {
                    #pragma unroll
                    for (int i = 0; i < 4; i++)
                        #pragma unroll
                        for (int h = 0; h < 2; h++)
                            sred[wcol*128 + wrow*64 + i*16 + (lane>>2) + h*8] = rt[i*2+h];
                }
                cpa_wait0();
                __syncthreads();
                if (tid < 128) {
                    int h = tid >> 6;
                    g_pos[br * 128 + tid] =
                        sred[(2*h)*128 + tid] + sred[(2*h+1)*128 + tid];
                }
                __syncthreads();
            } else {
                float cs[8];
                #pragma unroll
                for (int q = 0; q < 8; q++) cs[q] = 0.f;
                #pragma unroll
                for (int i = 0; i < 4; i++)
                    #pragma unroll
                    for (int j = 0; j < 4; j++) {
                        float e0 = fast_ex2(acc[i][j][0] * SCALE_L2E);
                        float e1 = fast_ex2(acc[i][j][1] * SCALE_L2E);
                        float e2 = fast_ex2(acc[i][j][2] * SCALE_L2E);
                        float e3 = fast_ex2(acc[i][j][3] * SCALE_L2E);
                        rs_acc[i*2]   += e0 + e1;
                        rs_acc[i*2+1] += e2 + e3;
                        cs[j*2]   += e0 + e2;
                        cs[j*2+1] += e1 + e3;
                    }
                #pragma unroll
                for (int q = 0; q < 8; q++) {
                    cs[q] += __shfl_xor_sync(m, cs[q], 4);
                    cs[q] += __shfl_xor_sync(m, cs[q], 8);
                    cs[q] += __shfl_xor_sync(m, cs[q], 16);
                }
                if (lane < 4) {
                    const int colbase = bc * 128 + wcol * 32 + lane * 2;
                    #pragma unroll
                    for (int j = 0; j < 4; j++) {
                        atomicAdd(&g_total[colbase + j * 8],     cs[j*2]);
                        atomicAdd(&g_total[colbase + j * 8 + 1], cs[j*2+1]);
                    }
                }
                cpa_wait0();
                __syncthreads();
            }

            t++; bc++;
            if (!next_same) break;
            buf ^= 1;
        }

        // flush accumulated row sums for band br
        __syncthreads();
        const unsigned m = 0xffffffffu;
        float rf[8];
        #pragma unroll
        for (int q = 0; q < 8; q++) {
            float v = rs_acc[q];
            v += __shfl_xor_sync(m, v, 1);
            v += __shfl_xor_sync(m, v, 2);
            rf[q] = v;
        }
        if ((lane & 3) == 0) {
            #pragma unroll
            for (int i = 0; i < 4; i++)
                #pragma unroll
                for (int h = 0; h < 2; h++)
                    sred[wcol*128 + wrow*64 + i*16 + (lane>>2) + h*8] = rf[i*2+h];
        }
        __syncthreads();
        if (tid < 128)
            atomicAdd(&g_total[br * 128 + tid],
                      sred[tid] + sred[128+tid] + sred[256+tid] + sred[384+tid]);
        __syncthreads();

        if (t < t1 && bc >= NT) { br++; bc = br; }
    }
}

// ---------------- Kernel 3: parallel loss ----------------------------------
__global__ void loss_kernel(float* __restrict__ out) {
    __shared__ float wsum[8];
    const int r = blockIdx.x * 256 + threadIdx.x;
    float s = __logf(g_total[r]) - __logf(g_pos[r]);
    #pragma unroll
    for (int o = 16; o; o >>= 1) s += __shfl_xor_sync(0xffffffffu, s, o);
    const int lane = threadIdx.x & 31, w = threadIdx.x >> 5;
    if (lane == 0) wsum[w] = s;
    __syncthreads();
    if (threadIdx.x == 0) {
        float bs = 0.f;
        #pragma unroll
        for (int i = 0; i < 8; i++) bs += wsum[i];
        atomicAdd(&g_loss, bs);
        __threadfence();
        unsigned old = atomicAdd(&g_cnt, 1u);
        if (old == gridDim.x - 1) {
            __threadfence();
            float tot = atomicAdd(&g_loss, 0.f);
            out[0] = tot / (float)N;
        }
    }
}

// ---------------- launch ----------------------------------------------------
extern "C" void kernel_launch(void* const* d_in, const int* in_sizes, int n_in,
                              void* d_out, int out_size) {
    const float* feature = (const float*)d_in[0];
    cudaFuncSetAttribute(gram_kernel,
                         cudaFuncAttributeMaxDynamicSharedMemorySize, SMEM_BYTES);
    normalize_kernel<<<N / 16, 256>>>(feature);
    gram_kernel<<<GRID, 256, SMEM_BYTES>>>();
    loss_kernel<<<32, 256>>>((float*)d_out);
}